// round 15
// baseline (speedup 1.0000x reference)
#include <cuda_runtime.h>
#include <math.h>

#define Bn 16
#define Sn 257
#define Hn 768
#define Vn 30522
#define Pn 32
#define Kn 8
#define NROWS (Bn * 256)
#define HALFV (Vn / 2)   // 15261 float2 per row; rows are always float2-aligned
#define GCAP 128         // per-row candidate capacity (expected ~41 used)

// Output layout (flat f32, reference tuple order)
#define OFF_COND 0
#define OFF_MARG 1
#define OFF_RM   2
#define OFF_SS   (OFF_RM + Bn * Vn)
#define OFF_MASK (OFF_SS + Bn * Vn)
#define OFF_RR   (OFF_MASK + Bn * 256)
#define OFF_IDS  (OFF_RR + Bn * Vn)
#define OFF_ER   (OFF_IDS + NROWS * Kn)
#define OFF_W    (OFF_ER + NROWS * Pn)

typedef unsigned long long u64;
typedef unsigned int u32;

__device__ float g_rowsum[NROWS];
__device__ float g_rowinv[NROWS];
__device__ int   g_cnt[NROWS];
__device__ u64   g_cand[(size_t)NROWS * GCAP];
__device__ float g_pos;

// spacers so pass1 lands at launch position 4 (the ncu capture slot)
__global__ void spacer_kernel() {}

// ---- monotone (value,index) packing: larger value first, ties -> smaller idx ----
__device__ __forceinline__ u64 packvi(float f, int idx) {
    u32 u = __float_as_uint(f);
    u = (u & 0x80000000u) ? ~u : (u | 0x80000000u);
    return ((u64)u << 32) | (u32)(0xFFFFFFFFu - (u32)idx);
}
__device__ __forceinline__ float unpackv(u64 p) {
    u32 k = (u32)(p >> 32);
    u32 u = (k & 0x80000000u) ? (k & 0x7FFFFFFFu) : ~k;
    return __uint_as_float(u);
}
__device__ __forceinline__ int unpacki(u64 p) {
    return (int)(0xFFFFFFFFu - (u32)p);
}

// Warp-distributed sorted top-8 insert: lanes 0..7 hold the list (lane0 =
// largest). pk must be warp-uniform.
__device__ __forceinline__ void winsert(u64& ldist, u64 pk, int lane) {
    u64 up = __shfl_up_sync(0xffffffffu, ldist, 1);
    if (lane == 0) up = ~0ull;                       // +inf sentinel
    ldist = (ldist >= pk) ? ldist : ((up >= pk) ? pk : up);
}

// ---------------- Kernel 1: pass1 — cols-shaped scan of logits ----------------
// Per (b, v-stripe) block, loop over s:
//   - exp of every element, per-warp shuffle reduce -> wsum[wid][s] (rowsum parts)
//   - masked max over s -> router_repr (written here)
//   - threshold-gather of top-8 candidates (>= T) into global per-row buffers
// No block sync inside the loop; same access pattern as the 82%-DRAM cols kernel.
__global__ __launch_bounds__(256) void pass1_kernel(const float* __restrict__ logits,
                                                    const float* __restrict__ attn,
                                                    float* __restrict__ out) {
    const int tid = threadIdx.x;
    const int b = blockIdx.y;
    const int pv = blockIdx.x * 256 + tid;
    const int lane = tid & 31;
    const int wid = tid >> 5;

    __shared__ float shon[256];
    __shared__ float wsum[8][256];
    shon[tid] = attn[b * Sn + 1 + tid] > 0.f ? 0.f : -INFINITY;  // additive mask
    __syncthreads();

    const bool act = (pv < HALFV);
    const float2* __restrict__ lp =
        (const float2*)(logits + ((size_t)b * Sn + 1) * Vn) + (act ? pv : 0);
    const int v0 = 2 * pv;
    const float T = 3.0f;
    float M0 = -INFINITY, M1 = -INFINITY;

#define P1(l, si)                                                            \
    {                                                                        \
        float _ex = act ? __expf((l).x) : 0.f;                               \
        float _ey = act ? __expf((l).y) : 0.f;                               \
        float _e = _ex + _ey;                                                \
        _e += __shfl_xor_sync(0xffffffffu, _e, 16);                          \
        _e += __shfl_xor_sync(0xffffffffu, _e, 8);                           \
        _e += __shfl_xor_sync(0xffffffffu, _e, 4);                           \
        _e += __shfl_xor_sync(0xffffffffu, _e, 2);                           \
        _e += __shfl_xor_sync(0xffffffffu, _e, 1);                           \
        if (lane == 0) wsum[wid][si] = _e;                                   \
        M0 = fmaxf(M0, (l).x + shon[si]);                                    \
        M1 = fmaxf(M1, (l).y + shon[si]);                                    \
        if (act && fmaxf((l).x, (l).y) >= T) {  /* rare */                   \
            int _r = b * 256 + (si);                                         \
            if ((l).x >= T) {                                                \
                int _p = atomicAdd(&g_cnt[_r], 1);                           \
                if (_p < GCAP) g_cand[(size_t)_r * GCAP + _p] = packvi((l).x, v0);     \
            }                                                                \
            if ((l).y >= T) {                                                \
                int _p = atomicAdd(&g_cnt[_r], 1);                           \
                if (_p < GCAP) g_cand[(size_t)_r * GCAP + _p] = packvi((l).y, v0 + 1); \
            }                                                                \
        }                                                                    \
    }

#pragma unroll 1
    for (int s = 0; s < 256; s += 8) {
        float2 l0 = __ldcs(lp + (size_t)(s + 0) * HALFV);
        float2 l1 = __ldcs(lp + (size_t)(s + 1) * HALFV);
        float2 l2 = __ldcs(lp + (size_t)(s + 2) * HALFV);
        float2 l3 = __ldcs(lp + (size_t)(s + 3) * HALFV);
        float2 l4 = __ldcs(lp + (size_t)(s + 4) * HALFV);
        float2 l5 = __ldcs(lp + (size_t)(s + 5) * HALFV);
        float2 l6 = __ldcs(lp + (size_t)(s + 6) * HALFV);
        float2 l7 = __ldcs(lp + (size_t)(s + 7) * HALFV);
        P1(l0, s + 0); P1(l1, s + 1); P1(l2, s + 2); P1(l3, s + 3);
        P1(l4, s + 4); P1(l5, s + 5); P1(l6, s + 6); P1(l7, s + 7);
    }

    if (act) {
        out[OFF_RR + b * Vn + v0]     = __logf(1.f + fmaxf(M0, 0.f));
        out[OFF_RR + b * Vn + v0 + 1] = __logf(1.f + fmaxf(M1, 0.f));
    }
    __syncthreads();

    // rowsum partial for s-row == tid: sum the 8 warp partials, one atomic
    float tot = 0.f;
#pragma unroll
    for (int w = 0; w < 8; w++) tot += wsum[w][tid];
    atomicAdd(&g_rowsum[b * 256 + tid], tot);
}

// ---------------- Kernel 2: topk — one warp per row ----------------
// rowinv = 1/rowsum; top-8 from the candidate buffer (fallback: full rescan
// for ANY pathological input); writes IDS / W / RM / g_pos.
__global__ __launch_bounds__(256) void topk_kernel(const float* __restrict__ logits,
                                                   const float* __restrict__ attn,
                                                   float* __restrict__ out) {
    const int lane = threadIdx.x & 31;
    const int wid = threadIdx.x >> 5;
    const int row = blockIdx.x * 8 + wid;
    const int b = row >> 8;
    const int s = row & 255;

    if (lane == 0) g_rowinv[row] = 1.f / g_rowsum[row];

    const int n = g_cnt[row];
    const u64 TINIT = packvi(-INFINITY, 0x7ffffffe);
    u64 ldist = TINIT;

    u64 t[Kn];
#pragma unroll
    for (int j = 0; j < Kn; j++) t[j] = TINIT;

    if (n >= Kn && n <= GCAP) {
        // gather candidates (<=4 per lane), per-lane sorted insert
        for (int i = lane; i < n; i += 32) {
            u64 pk = g_cand[(size_t)row * GCAP + i];
            if (pk > t[Kn - 1]) {
                u64 x = pk;
#pragma unroll
                for (int j = 0; j < Kn; j++) {
                    if (x > t[j]) { u64 tmp = t[j]; t[j] = x; x = tmp; }
                }
            }
        }
    } else {
        // fallback (statistically never): full scalar rescan of the row
        const float* __restrict__ rowp = logits + ((size_t)b * Sn + (s + 1)) * Vn;
        for (int q = lane; q < Vn; q += 32) {
            u64 pk = packvi(rowp[q], q);
            if (pk > t[Kn - 1]) {
                u64 x = pk;
#pragma unroll
                for (int j = 0; j < Kn; j++) {
                    if (x > t[j]) { u64 tmp = t[j]; t[j] = x; x = tmp; }
                }
            }
        }
    }
    // merge 32 sorted lists via repeated warp-max
    {
        int head = 0;
#pragma unroll
        for (int k = 0; k < Kn; k++) {
            u64 c = (head < Kn) ? t[head] : 0ull;
#pragma unroll
            for (int offs = 16; offs; offs >>= 1) {
                u64 o = __shfl_xor_sync(0xffffffffu, c, offs);
                if (o > c) c = o;
            }
            if (head < Kn && t[head] == c) head++;
            winsert(ldist, c, lane);
        }
    }

    const float mk = attn[b * Sn + s + 1];
    if (lane < Kn) {
        float lgk = unpackv(ldist);
        int id = unpacki(ldist);
        float w; int oid;
        if (mk > 0.f) { w = __logf(1.f + fmaxf(lgk, 0.f)) * mk; oid = id; }
        else          { w = 0.f; oid = lane; }
        out[OFF_IDS + row * Kn + lane] = (float)oid;
        out[OFF_W   + row * Kn + lane] = w;
        if (w > 0.f) {
            atomicAdd(&out[OFF_RM + b * Vn + id], 1.f);
            atomicAdd(&g_pos, 1.f);
        }
    }
}

// ---------------- Kernel 3: pass2 — softmax-sum + fused finalize ----------------
// Runs after topk: rowinv / RM / g_pos complete. Writes SS + COND/MARG.
__global__ __launch_bounds__(256) void pass2_kernel(const float* __restrict__ logits,
                                                    float* __restrict__ out) {
    const int tid = threadIdx.x;
    const int b = blockIdx.y;
    const int pv = blockIdx.x * 256 + tid;
    const int lane = tid & 31;

    __shared__ float shi[256];
    shi[tid] = g_rowinv[b * 256 + tid];

    // fused finalize (b==0 plane covers all v)
    if (b == 0) {
        float mxa = 0.f, mxb = 0.f;
        if (pv < HALFV) {
            int v0 = 2 * pv;
#pragma unroll
            for (int bb = 0; bb < Bn; bb++) {
                mxa = fmaxf(mxa, out[OFF_RM + bb * Vn + v0]);
                mxb = fmaxf(mxb, out[OFF_RM + bb * Vn + v0 + 1]);
            }
        }
        float tot = mxa + mxb;
#pragma unroll
        for (int offs = 16; offs; offs >>= 1) tot += __shfl_xor_sync(0xffffffffu, tot, offs);
        if (lane == 0 && tot != 0.f) atomicAdd(&out[OFF_MARG], tot);
        if (blockIdx.x == 0 && tid == 0) out[OFF_COND] = g_pos * (1.f / Bn);
    }

    __syncthreads();
    if (pv >= HALFV) return;

    const float2* __restrict__ lp =
        (const float2*)(logits + ((size_t)b * Sn + 1) * Vn) + pv;
    float a0 = 0.f, a1 = 0.f, a2 = 0.f, a3 = 0.f;
#pragma unroll 1
    for (int s = 0; s < 256; s += 8) {
        float2 l0 = __ldcs(lp + (size_t)(s + 0) * HALFV);
        float2 l1 = __ldcs(lp + (size_t)(s + 1) * HALFV);
        float2 l2 = __ldcs(lp + (size_t)(s + 2) * HALFV);
        float2 l3 = __ldcs(lp + (size_t)(s + 3) * HALFV);
        float2 l4 = __ldcs(lp + (size_t)(s + 4) * HALFV);
        float2 l5 = __ldcs(lp + (size_t)(s + 5) * HALFV);
        float2 l6 = __ldcs(lp + (size_t)(s + 6) * HALFV);
        float2 l7 = __ldcs(lp + (size_t)(s + 7) * HALFV);
        a0 += __expf(l0.x) * shi[s + 0];  a1 += __expf(l0.y) * shi[s + 0];
        a2 += __expf(l1.x) * shi[s + 1];  a3 += __expf(l1.y) * shi[s + 1];
        a0 += __expf(l2.x) * shi[s + 2];  a1 += __expf(l2.y) * shi[s + 2];
        a2 += __expf(l3.x) * shi[s + 3];  a3 += __expf(l3.y) * shi[s + 3];
        a0 += __expf(l4.x) * shi[s + 4];  a1 += __expf(l4.y) * shi[s + 4];
        a2 += __expf(l5.x) * shi[s + 5];  a3 += __expf(l5.y) * shi[s + 5];
        a0 += __expf(l6.x) * shi[s + 6];  a1 += __expf(l6.y) * shi[s + 6];
        a2 += __expf(l7.x) * shi[s + 7];  a3 += __expf(l7.y) * shi[s + 7];
    }
    int v = 2 * pv;
    out[OFF_SS + b * Vn + v]     = (a0 + a2);
    out[OFF_SS + b * Vn + v + 1] = (a1 + a3);
}

// ---------------- Kernel C: expert_repr + fused zeroing ----------------
#define EK_ROWS 4
__global__ __launch_bounds__(256) void expert_kernel(const float* __restrict__ hidden,
                                                     const float* __restrict__ attn,
                                                     const float* __restrict__ W,
                                                     const float* __restrict__ bt,
                                                     float* __restrict__ out) {
    // fused zero: COND/MARG/RM region + g_rowsum/g_cnt/g_pos scratch
    {
        int gidx = blockIdx.x * 256 + threadIdx.x;
        if (gidx < OFF_SS) out[gidx] = 0.f;
        int g2 = gidx + (NROWS / EK_ROWS) * 256;
        if (g2 < OFF_SS) out[g2] = 0.f;
        if (gidx < NROWS) { g_rowsum[gidx] = 0.f; g_cnt[gidx] = 0; }
        if (gidx == 0) g_pos = 0.f;
    }

    __shared__ float hrow[Hn];
    const int tid = threadIdx.x;
    const int lane = tid & 31;
    const int wid = tid >> 5;
    const int p0 = wid * 4;

    const float* __restrict__ w0 = W + (p0 + 0) * Hn + lane;
    const float* __restrict__ w1 = W + (p0 + 1) * Hn + lane;
    const float* __restrict__ w2 = W + (p0 + 2) * Hn + lane;
    const float* __restrict__ w3 = W + (p0 + 3) * Hn + lane;

    for (int r = 0; r < EK_ROWS; r++) {
        const int row = blockIdx.x * EK_ROWS + r;
        const int b = row >> 8;
        const int s = row & 255;
        const size_t hbase = ((size_t)b * Sn + s + 1) * Hn;
#pragma unroll
        for (int c = 0; c < 3; c++) hrow[c * 256 + tid] = hidden[hbase + c * 256 + tid];
        __syncthreads();

        float a0 = 0.f, a1 = 0.f, a2 = 0.f, a3 = 0.f;
#pragma unroll
        for (int k = 0; k < Hn / 32; k++) {
            float hv = hrow[k * 32 + lane];
            a0 += hv * __ldg(w0 + k * 32);
            a1 += hv * __ldg(w1 + k * 32);
            a2 += hv * __ldg(w2 + k * 32);
            a3 += hv * __ldg(w3 + k * 32);
        }
#pragma unroll
        for (int off = 16; off; off >>= 1) {
            a0 += __shfl_xor_sync(0xffffffffu, a0, off);
            a1 += __shfl_xor_sync(0xffffffffu, a1, off);
            a2 += __shfl_xor_sync(0xffffffffu, a2, off);
            a3 += __shfl_xor_sync(0xffffffffu, a3, off);
        }
        if (lane == 0) {
            float mk = attn[b * Sn + s + 1];
            if (wid == 0) out[OFF_MASK + row] = mk;
            out[OFF_ER + row * Pn + p0 + 0] = (a0 + bt[p0 + 0]) * mk;
            out[OFF_ER + row * Pn + p0 + 1] = (a1 + bt[p0 + 1]) * mk;
            out[OFF_ER + row * Pn + p0 + 2] = (a2 + bt[p0 + 2]) * mk;
            out[OFF_ER + row * Pn + p0 + 3] = (a3 + bt[p0 + 3]) * mk;
        }
        __syncthreads();
    }
}

extern "C" void kernel_launch(void* const* d_in, const int* in_sizes, int n_in,
                              void* d_out, int out_size) {
    const float *hidden = nullptr, *logits = nullptr, *attn = nullptr, *W = nullptr, *bt = nullptr;
    for (int i = 0; i < n_in; i++) {
        long n = in_sizes[i];
        if      (n == (long)Bn * Sn * Vn) logits = (const float*)d_in[i];
        else if (n == (long)Bn * Sn * Hn) hidden = (const float*)d_in[i];
        else if (n == (long)Bn * Sn)      attn   = (const float*)d_in[i];
        else if (n == (long)Pn * Hn)      W      = (const float*)d_in[i];
        else if (n == (long)Pn)           bt     = (const float*)d_in[i];
    }
    float* out = (float*)d_out;

    dim3 vgrid((HALFV + 255) / 256, Bn);
    expert_kernel<<<NROWS / EK_ROWS, 256>>>(hidden, attn, W, bt, out);  // 1 (+zero)
    spacer_kernel<<<1, 32>>>();                                         // 2
    spacer_kernel<<<1, 32>>>();                                         // 3
    pass1_kernel<<<vgrid, 256>>>(logits, attn, out);                    // 4 (profiled)
    topk_kernel<<<NROWS / 8, 256>>>(logits, attn, out);                 // 5
    pass2_kernel<<<vgrid, 256>>>(logits, out);                          // 6 (+finalize)
}

// round 16
// speedup vs baseline: 1.1511x; 1.1511x over previous
#include <cuda_runtime.h>
#include <math.h>

#define Bn 16
#define Sn 257
#define Hn 768
#define Vn 30522
#define Pn 32
#define Kn 8
#define NROWS (Bn * 256)
#define HALFV (Vn / 2)        // 15261 float2 per row
#define GCAP 128              // per-row candidate capacity (expected ~41 used)
#define E4 ((size_t)Bn * Sn * Vn / 4)   // 31,376,616 float4 in the whole tensor
#define SB4 2048              // float4 per sums block (8192 floats)

// Output layout (flat f32, reference tuple order)
#define OFF_COND 0
#define OFF_MARG 1
#define OFF_RM   2
#define OFF_SS   (OFF_RM + Bn * Vn)
#define OFF_MASK (OFF_SS + Bn * Vn)
#define OFF_RR   (OFF_MASK + Bn * 256)
#define OFF_IDS  (OFF_RR + Bn * Vn)
#define OFF_ER   (OFF_IDS + NROWS * Kn)
#define OFF_W    (OFF_ER + NROWS * Pn)

typedef unsigned long long u64;
typedef unsigned int u32;

__device__ float g_rowsum[NROWS];
__device__ int   g_cnt[NROWS];
__device__ u64   g_cand[(size_t)NROWS * GCAP];
__device__ float g_pos;

// spacers so sums_kernel lands at launch position 4 (the ncu capture slot)
__global__ void spacer_kernel() {}

// ---- monotone (value,index) packing: larger value first, ties -> smaller idx ----
__device__ __forceinline__ u64 packvi(float f, int idx) {
    u32 u = __float_as_uint(f);
    u = (u & 0x80000000u) ? ~u : (u | 0x80000000u);
    return ((u64)u << 32) | (u32)(0xFFFFFFFFu - (u32)idx);
}
__device__ __forceinline__ float unpackv(u64 p) {
    u32 k = (u32)(p >> 32);
    u32 u = (k & 0x80000000u) ? (k & 0x7FFFFFFFu) : ~k;
    return __uint_as_float(u);
}
__device__ __forceinline__ int unpacki(u64 p) {
    return (int)(0xFFFFFFFFu - (u32)p);
}

// Warp-distributed sorted top-8 insert: lanes 0..7 hold the list (lane0 =
// largest). pk must be warp-uniform.
__device__ __forceinline__ void winsert(u64& ldist, u64 pk, int lane) {
    u64 up = __shfl_up_sync(0xffffffffu, ldist, 1);
    if (lane == 0) up = ~0ull;                       // +inf sentinel
    ldist = (ldist >= pk) ? ldist : ((up >= pk) ? pk : up);
}

// global row index (b*Sn + s') -> output row, or -1 for the s'==0 plane
__device__ __forceinline__ int orow_of(u32 r) {
    u32 bb = r / (u32)Sn;
    u32 ss = r - bb * (u32)Sn;
    return (ss == 0) ? -1 : (int)(bb * 256 + ss - 1);
}

// ---------------- Kernel 1: sums — flat segmented sum-of-exp ----------------
// Pure streaming: each block covers 8192 CONTIGUOUS floats (<= 2 rows).
// Row membership = one boundary compare (no division in the loop, no
// cross-thread ops). Two atomics per block. memcpy-class shape.
__global__ __launch_bounds__(256) void sums_kernel(const float* __restrict__ logits) {
    const int tid = threadIdx.x;
    const int lane = tid & 31;
    const int wid = tid >> 5;
    const size_t base4 = (size_t)blockIdx.x * SB4;
    const float4* __restrict__ lp4 = (const float4*)logits;

    const u32 r0 = (u32)((base4 * 4) / Vn);          // first global row in block
    const size_t bnd = (size_t)(r0 + 1) * Vn;        // float index where row r0+1 starts

    // front-batched loads (guarded only in the tail block)
    float4 v[8];
    const bool full = (base4 + SB4 <= E4);
#pragma unroll
    for (int j = 0; j < 8; j++) {
        size_t i4 = base4 + (size_t)j * 256 + tid;
        v[j] = (full || i4 < E4) ? __ldcs(lp4 + i4)
                                 : make_float4(-INFINITY, -INFINITY, -INFINITY, -INFINITY);
    }

    float accA = 0.f, accB = 0.f;
#pragma unroll
    for (int j = 0; j < 8; j++) {
        size_t fi = (base4 + (size_t)j * 256 + tid) * 4;
        float e0 = __expf(v[j].x), e1 = __expf(v[j].y);
        float e2 = __expf(v[j].z), e3 = __expf(v[j].w);
        float sm = (e0 + e1) + (e2 + e3);
        if (fi + 4 <= bnd)      accA += sm;           // common path
        else if (fi >= bnd)     accB += sm;           // common path
        else {                                        // <=1 straddling float4 / thread
            accA += (fi + 0 < bnd) ? e0 : 0.f;  accB += (fi + 0 >= bnd) ? e0 : 0.f;
            accA += (fi + 1 < bnd) ? e1 : 0.f;  accB += (fi + 1 >= bnd) ? e1 : 0.f;
            accA += (fi + 2 < bnd) ? e2 : 0.f;  accB += (fi + 2 >= bnd) ? e2 : 0.f;
            accA += (fi + 3 < bnd) ? e3 : 0.f;  accB += (fi + 3 >= bnd) ? e3 : 0.f;
        }
    }

#pragma unroll
    for (int o = 16; o; o >>= 1) {
        accA += __shfl_xor_sync(0xffffffffu, accA, o);
        accB += __shfl_xor_sync(0xffffffffu, accB, o);
    }
    __shared__ float sA[8], sB[8];
    if (lane == 0) { sA[wid] = accA; sB[wid] = accB; }
    __syncthreads();
    if (tid == 0) {
        float a = 0.f;
#pragma unroll
        for (int w = 0; w < 8; w++) a += sA[w];
        int oa = orow_of(r0);
        if (oa >= 0 && a != 0.f) atomicAdd(&g_rowsum[oa], a);
    }
    if (tid == 1) {
        float bsum = 0.f;
#pragma unroll
        for (int w = 0; w < 8; w++) bsum += sB[w];
        if (bsum != 0.f && r0 + 1 < (u32)(Bn * Sn)) {
            int ob = orow_of(r0 + 1);
            if (ob >= 0) atomicAdd(&g_rowsum[ob], bsum);
        }
    }
}

// ---------------- Kernel 2: cols — SS + RR + candidate gather ----------------
// R12's proven 82%-DRAM shape. Adds: inline 1/rowsum, and a top-8 candidate
// gather behind ONE merged branch per 16 elements (~1 extra op/element).
__global__ __launch_bounds__(256) void cols_kernel(const float* __restrict__ logits,
                                                   const float* __restrict__ attn,
                                                   float* __restrict__ out) {
    const int tid = threadIdx.x;
    const int b = blockIdx.y;
    const int pv = blockIdx.x * 256 + tid;

    __shared__ float shi[256];
    __shared__ float shon[256];
    shi[tid]  = 1.f / g_rowsum[b * 256 + tid];
    shon[tid] = attn[b * Sn + 1 + tid] > 0.f ? 0.f : -INFINITY;  // additive mask
    __syncthreads();
    if (pv >= HALFV) return;

    const float2* __restrict__ lp =
        (const float2*)(logits + ((size_t)b * Sn + 1) * Vn) + pv;
    const int v0 = 2 * pv;
    const float T = 3.0f;
    float M0 = -INFINITY, M1 = -INFINITY;
    float a0 = 0.f, a1 = 0.f, a2 = 0.f, a3 = 0.f;

#define PUSHC(f, vv, si)                                                     \
    {                                                                        \
        int _r = b * 256 + (si);                                             \
        int _p = atomicAdd(&g_cnt[_r], 1);                                   \
        if (_p < GCAP) g_cand[(size_t)_r * GCAP + _p] = packvi((f), (vv));   \
    }
#define CHK(l, si)                                                           \
    {                                                                        \
        if ((l).x >= T) PUSHC((l).x, v0, si);                                \
        if ((l).y >= T) PUSHC((l).y, v0 + 1, si);                            \
    }

#pragma unroll 1
    for (int s = 0; s < 256; s += 8) {
        float2 l0 = __ldcs(lp + (size_t)(s + 0) * HALFV);
        float2 l1 = __ldcs(lp + (size_t)(s + 1) * HALFV);
        float2 l2 = __ldcs(lp + (size_t)(s + 2) * HALFV);
        float2 l3 = __ldcs(lp + (size_t)(s + 3) * HALFV);
        float2 l4 = __ldcs(lp + (size_t)(s + 4) * HALFV);
        float2 l5 = __ldcs(lp + (size_t)(s + 5) * HALFV);
        float2 l6 = __ldcs(lp + (size_t)(s + 6) * HALFV);
        float2 l7 = __ldcs(lp + (size_t)(s + 7) * HALFV);
        a0 += __expf(l0.x) * shi[s + 0];  a1 += __expf(l0.y) * shi[s + 0];
        a2 += __expf(l1.x) * shi[s + 1];  a3 += __expf(l1.y) * shi[s + 1];
        a0 += __expf(l2.x) * shi[s + 2];  a1 += __expf(l2.y) * shi[s + 2];
        a2 += __expf(l3.x) * shi[s + 3];  a3 += __expf(l3.y) * shi[s + 3];
        a0 += __expf(l4.x) * shi[s + 4];  a1 += __expf(l4.y) * shi[s + 4];
        a2 += __expf(l5.x) * shi[s + 5];  a3 += __expf(l5.y) * shi[s + 5];
        a0 += __expf(l6.x) * shi[s + 6];  a1 += __expf(l6.y) * shi[s + 6];
        a2 += __expf(l7.x) * shi[s + 7];  a3 += __expf(l7.y) * shi[s + 7];
        float x0 = fmaxf(l0.x, l0.y), x1 = fmaxf(l1.x, l1.y);
        float x2 = fmaxf(l2.x, l2.y), x3 = fmaxf(l3.x, l3.y);
        float x4 = fmaxf(l4.x, l4.y), x5 = fmaxf(l5.x, l5.y);
        float x6 = fmaxf(l6.x, l6.y), x7 = fmaxf(l7.x, l7.y);
        M0 = fmaxf(M0, l0.x + shon[s + 0]);  M1 = fmaxf(M1, l0.y + shon[s + 0]);
        M0 = fmaxf(M0, l1.x + shon[s + 1]);  M1 = fmaxf(M1, l1.y + shon[s + 1]);
        M0 = fmaxf(M0, l2.x + shon[s + 2]);  M1 = fmaxf(M1, l2.y + shon[s + 2]);
        M0 = fmaxf(M0, l3.x + shon[s + 3]);  M1 = fmaxf(M1, l3.y + shon[s + 3]);
        M0 = fmaxf(M0, l4.x + shon[s + 4]);  M1 = fmaxf(M1, l4.y + shon[s + 4]);
        M0 = fmaxf(M0, l5.x + shon[s + 5]);  M1 = fmaxf(M1, l5.y + shon[s + 5]);
        M0 = fmaxf(M0, l6.x + shon[s + 6]);  M1 = fmaxf(M1, l6.y + shon[s + 6]);
        M0 = fmaxf(M0, l7.x + shon[s + 7]);  M1 = fmaxf(M1, l7.y + shon[s + 7]);
        float mall = fmaxf(fmaxf(fmaxf(x0, x1), fmaxf(x2, x3)),
                           fmaxf(fmaxf(x4, x5), fmaxf(x6, x7)));
        if (mall >= T) {  /* ~2% of steps */
            CHK(l0, s + 0); CHK(l1, s + 1); CHK(l2, s + 2); CHK(l3, s + 3);
            CHK(l4, s + 4); CHK(l5, s + 5); CHK(l6, s + 6); CHK(l7, s + 7);
        }
    }
    out[OFF_RR + b * Vn + v0]     = __logf(1.f + fmaxf(M0, 0.f));
    out[OFF_RR + b * Vn + v0 + 1] = __logf(1.f + fmaxf(M1, 0.f));
    out[OFF_SS + b * Vn + v0]     = (a0 + a2);
    out[OFF_SS + b * Vn + v0 + 1] = (a1 + a3);
}

// ---------------- Kernel 3: topk — one warp per row ----------------
// top-8 from the candidate buffer (fallback: full rescan for ANY pathological
// input); writes IDS / W / RM / g_pos.
__global__ __launch_bounds__(256) void topk_kernel(const float* __restrict__ logits,
                                                   const float* __restrict__ attn,
                                                   float* __restrict__ out) {
    const int lane = threadIdx.x & 31;
    const int wid = threadIdx.x >> 5;
    const int row = blockIdx.x * 8 + wid;
    const int b = row >> 8;
    const int s = row & 255;

    const int n = g_cnt[row];
    const u64 TINIT = packvi(-INFINITY, 0x7ffffffe);
    u64 ldist = TINIT;

    u64 t[Kn];
#pragma unroll
    for (int j = 0; j < Kn; j++) t[j] = TINIT;

    if (n >= Kn && n <= GCAP) {
        for (int i = lane; i < n; i += 32) {
            u64 pk = g_cand[(size_t)row * GCAP + i];
            if (pk > t[Kn - 1]) {
                u64 x = pk;
#pragma unroll
                for (int j = 0; j < Kn; j++) {
                    if (x > t[j]) { u64 tmp = t[j]; t[j] = x; x = tmp; }
                }
            }
        }
    } else {
        // fallback (statistically never): full scalar rescan of the row
        const float* __restrict__ rowp = logits + ((size_t)b * Sn + (s + 1)) * Vn;
        for (int q = lane; q < Vn; q += 32) {
            u64 pk = packvi(rowp[q], q);
            if (pk > t[Kn - 1]) {
                u64 x = pk;
#pragma unroll
                for (int j = 0; j < Kn; j++) {
                    if (x > t[j]) { u64 tmp = t[j]; t[j] = x; x = tmp; }
                }
            }
        }
    }
    // merge 32 sorted lists via repeated warp-max
    {
        int head = 0;
#pragma unroll
        for (int k = 0; k < Kn; k++) {
            u64 c = (head < Kn) ? t[head] : 0ull;
#pragma unroll
            for (int offs = 16; offs; offs >>= 1) {
                u64 o = __shfl_xor_sync(0xffffffffu, c, offs);
                if (o > c) c = o;
            }
            if (head < Kn && t[head] == c) head++;
            winsert(ldist, c, lane);
        }
    }

    const float mk = attn[b * Sn + s + 1];
    if (lane < Kn) {
        float lgk = unpackv(ldist);
        int id = unpacki(ldist);
        float w; int oid;
        if (mk > 0.f) { w = __logf(1.f + fmaxf(lgk, 0.f)) * mk; oid = id; }
        else          { w = 0.f; oid = lane; }
        out[OFF_IDS + row * Kn + lane] = (float)oid;
        out[OFF_W   + row * Kn + lane] = w;
        if (w > 0.f) {
            atomicAdd(&out[OFF_RM + b * Vn + id], 1.f);
            atomicAdd(&g_pos, 1.f);
        }
    }
}

// ---------------- Kernel 4: fin — avg_cond / avg_marg ----------------
__global__ __launch_bounds__(256) void fin_kernel(float* __restrict__ out) {
    const int tid = threadIdx.x;
    int v = blockIdx.x * 256 + tid;
    float mx = 0.f;
    if (v < Vn) {
#pragma unroll
        for (int b = 0; b < Bn; b++) mx = fmaxf(mx, out[OFF_RM + b * Vn + v]);
    }
    __shared__ float red[256];
    red[tid] = mx; __syncthreads();
    for (int off = 128; off > 0; off >>= 1) {
        if (tid < off) red[tid] += red[tid + off];
        __syncthreads();
    }
    if (tid == 0) atomicAdd(&out[OFF_MARG], red[0]);
    if (blockIdx.x == 0 && tid == 0) out[OFF_COND] = g_pos * (1.f / Bn);
}

// ---------------- Kernel 5: expert_repr + fused zeroing ----------------
#define EK_ROWS 4
__global__ __launch_bounds__(256) void expert_kernel(const float* __restrict__ hidden,
                                                     const float* __restrict__ attn,
                                                     const float* __restrict__ W,
                                                     const float* __restrict__ bt,
                                                     float* __restrict__ out) {
    // fused zero: COND/MARG/RM region + g_rowsum/g_cnt/g_pos scratch
    {
        int gidx = blockIdx.x * 256 + threadIdx.x;
        if (gidx < OFF_SS) out[gidx] = 0.f;
        int g2 = gidx + (NROWS / EK_ROWS) * 256;
        if (g2 < OFF_SS) out[g2] = 0.f;
        if (gidx < NROWS) { g_rowsum[gidx] = 0.f; g_cnt[gidx] = 0; }
        if (gidx == 0) g_pos = 0.f;
    }

    __shared__ float hrow[Hn];
    const int tid = threadIdx.x;
    const int lane = tid & 31;
    const int wid = tid >> 5;
    const int p0 = wid * 4;

    const float* __restrict__ w0 = W + (p0 + 0) * Hn + lane;
    const float* __restrict__ w1 = W + (p0 + 1) * Hn + lane;
    const float* __restrict__ w2 = W + (p0 + 2) * Hn + lane;
    const float* __restrict__ w3 = W + (p0 + 3) * Hn + lane;

    for (int r = 0; r < EK_ROWS; r++) {
        const int row = blockIdx.x * EK_ROWS + r;
        const int b = row >> 8;
        const int s = row & 255;
        const size_t hbase = ((size_t)b * Sn + s + 1) * Hn;
#pragma unroll
        for (int c = 0; c < 3; c++) hrow[c * 256 + tid] = hidden[hbase + c * 256 + tid];
        __syncthreads();

        float a0 = 0.f, a1 = 0.f, a2 = 0.f, a3 = 0.f;
#pragma unroll
        for (int k = 0; k < Hn / 32; k++) {
            float hv = hrow[k * 32 + lane];
            a0 += hv * __ldg(w0 + k * 32);
            a1 += hv * __ldg(w1 + k * 32);
            a2 += hv * __ldg(w2 + k * 32);
            a3 += hv * __ldg(w3 + k * 32);
        }
#pragma unroll
        for (int off = 16; off; off >>= 1) {
            a0 += __shfl_xor_sync(0xffffffffu, a0, off);
            a1 += __shfl_xor_sync(0xffffffffu, a1, off);
            a2 += __shfl_xor_sync(0xffffffffu, a2, off);
            a3 += __shfl_xor_sync(0xffffffffu, a3, off);
        }
        if (lane == 0) {
            float mk = attn[b * Sn + s + 1];
            if (wid == 0) out[OFF_MASK + row] = mk;
            out[OFF_ER + row * Pn + p0 + 0] = (a0 + bt[p0 + 0]) * mk;
            out[OFF_ER + row * Pn + p0 + 1] = (a1 + bt[p0 + 1]) * mk;
            out[OFF_ER + row * Pn + p0 + 2] = (a2 + bt[p0 + 2]) * mk;
            out[OFF_ER + row * Pn + p0 + 3] = (a3 + bt[p0 + 3]) * mk;
        }
        __syncthreads();
    }
}

extern "C" void kernel_launch(void* const* d_in, const int* in_sizes, int n_in,
                              void* d_out, int out_size) {
    const float *hidden = nullptr, *logits = nullptr, *attn = nullptr, *W = nullptr, *bt = nullptr;
    for (int i = 0; i < n_in; i++) {
        long n = in_sizes[i];
        if      (n == (long)Bn * Sn * Vn) logits = (const float*)d_in[i];
        else if (n == (long)Bn * Sn * Hn) hidden = (const float*)d_in[i];
        else if (n == (long)Bn * Sn)      attn   = (const float*)d_in[i];
        else if (n == (long)Pn * Hn)      W      = (const float*)d_in[i];
        else if (n == (long)Pn)           bt     = (const float*)d_in[i];
    }
    float* out = (float*)d_out;

    const int nsum = (int)((E4 + SB4 - 1) / SB4);     // 15321
    dim3 vgrid((HALFV + 255) / 256, Bn);

    expert_kernel<<<NROWS / EK_ROWS, 256>>>(hidden, attn, W, bt, out);  // 1 (+zero)
    spacer_kernel<<<1, 32>>>();                                         // 2
    spacer_kernel<<<1, 32>>>();                                         // 3
    sums_kernel<<<nsum, 256>>>(logits);                                 // 4 (profiled)
    cols_kernel<<<vgrid, 256>>>(logits, attn, out);                     // 5 (+gather)
    topk_kernel<<<NROWS / 8, 256>>>(logits, attn, out);                 // 6
    fin_kernel<<<(Vn + 255) / 256, 256>>>(out);                         // 7
}

// round 17
// speedup vs baseline: 1.2966x; 1.1264x over previous
#include <cuda_runtime.h>
#include <math.h>

#define Bn 16
#define Sn 257
#define Hn 768
#define Vn 30522
#define Pn 32
#define Kn 8
#define NROWS (Bn * 256)
#define HALFV (Vn / 2)        // 15261 float2 per row
#define GCAP 128              // per-row candidate capacity (expected ~41 used)
#define E4 ((size_t)Bn * Sn * Vn / 4)   // 31,376,616 float4 in the whole tensor
#define SB4 2048              // float4 per sums block (8192 floats)

// Output layout (flat f32, reference tuple order)
#define OFF_COND 0
#define OFF_MARG 1
#define OFF_RM   2
#define OFF_SS   (OFF_RM + Bn * Vn)
#define OFF_MASK (OFF_SS + Bn * Vn)
#define OFF_RR   (OFF_MASK + Bn * 256)
#define OFF_IDS  (OFF_RR + Bn * Vn)
#define OFF_ER   (OFF_IDS + NROWS * Kn)
#define OFF_W    (OFF_ER + NROWS * Pn)

typedef unsigned long long u64;
typedef unsigned int u32;

__device__ float g_rowsum[NROWS];
__device__ int   g_cnt[NROWS];
__device__ u64   g_cand[(size_t)NROWS * GCAP];
__device__ float g_pos;

// spacers so sums_kernel lands at launch position 4 (the ncu capture slot)
__global__ void spacer_kernel() {}

// ---- monotone (value,index) packing: larger value first, ties -> smaller idx ----
__device__ __forceinline__ u64 packvi(float f, int idx) {
    u32 u = __float_as_uint(f);
    u = (u & 0x80000000u) ? ~u : (u | 0x80000000u);
    return ((u64)u << 32) | (u32)(0xFFFFFFFFu - (u32)idx);
}
__device__ __forceinline__ float unpackv(u64 p) {
    u32 k = (u32)(p >> 32);
    u32 u = (k & 0x80000000u) ? (k & 0x7FFFFFFFu) : ~k;
    return __uint_as_float(u);
}
__device__ __forceinline__ int unpacki(u64 p) {
    return (int)(0xFFFFFFFFu - (u32)p);
}

// Warp-distributed sorted top-8 insert: lanes 0..7 hold the list (lane0 =
// largest). pk must be warp-uniform.
__device__ __forceinline__ void winsert(u64& ldist, u64 pk, int lane) {
    u64 up = __shfl_up_sync(0xffffffffu, ldist, 1);
    if (lane == 0) up = ~0ull;                       // +inf sentinel
    ldist = (ldist >= pk) ? ldist : ((up >= pk) ? pk : up);
}

// global row index (b*Sn + s') -> output row, or -1 for the s'==0 plane
__device__ __forceinline__ int orow_of(u32 r) {
    u32 bb = r / (u32)Sn;
    u32 ss = r - bb * (u32)Sn;
    return (ss == 0) ? -1 : (int)(bb * 256 + ss - 1);
}

// ---------------- Kernel 1: sums — flat sum-of-exp + candidate gather ----------------
// Pure streaming (82% DRAM measured in R16): each block covers 8192
// CONTIGUOUS floats (<= 2 rows). Row membership = one boundary compare.
// Candidate gather added on the RARE path only (threshold T; row/column
// recovered by division inside the rare branch).
__global__ __launch_bounds__(256) void sums_kernel(const float* __restrict__ logits) {
    const int tid = threadIdx.x;
    const int lane = tid & 31;
    const int wid = tid >> 5;
    const size_t base4 = (size_t)blockIdx.x * SB4;
    const float4* __restrict__ lp4 = (const float4*)logits;

    const u32 r0 = (u32)((base4 * 4) / Vn);          // first global row in block
    const size_t bnd = (size_t)(r0 + 1) * Vn;        // float index where row r0+1 starts
    const float T = 3.0f;

    // front-batched loads (guarded only in the tail block)
    float4 v[8];
    const bool full = (base4 + SB4 <= E4);
#pragma unroll
    for (int j = 0; j < 8; j++) {
        size_t i4 = base4 + (size_t)j * 256 + tid;
        v[j] = (full || i4 < E4) ? __ldcs(lp4 + i4)
                                 : make_float4(-INFINITY, -INFINITY, -INFINITY, -INFINITY);
    }

    float accA = 0.f, accB = 0.f;
#pragma unroll
    for (int j = 0; j < 8; j++) {
        size_t fi = (base4 + (size_t)j * 256 + tid) * 4;
        float e0 = __expf(v[j].x), e1 = __expf(v[j].y);
        float e2 = __expf(v[j].z), e3 = __expf(v[j].w);
        float sm = (e0 + e1) + (e2 + e3);
        if (fi + 4 <= bnd)      accA += sm;           // common path
        else if (fi >= bnd)     accB += sm;           // common path
        else {                                        // <=1 straddling float4 / thread
            accA += (fi + 0 < bnd) ? e0 : 0.f;  accB += (fi + 0 >= bnd) ? e0 : 0.f;
            accA += (fi + 1 < bnd) ? e1 : 0.f;  accB += (fi + 1 >= bnd) ? e1 : 0.f;
            accA += (fi + 2 < bnd) ? e2 : 0.f;  accB += (fi + 2 >= bnd) ? e2 : 0.f;
            accA += (fi + 3 < bnd) ? e3 : 0.f;  accB += (fi + 3 >= bnd) ? e3 : 0.f;
        }
        // candidate gather (rare: ~1 float4 in 190 passes the test)
        float mx = fmaxf(fmaxf(v[j].x, v[j].y), fmaxf(v[j].z, v[j].w));
        if (mx >= T) {
#pragma unroll
            for (int h = 0; h < 4; h++) {
                float f = (h == 0) ? v[j].x : (h == 1) ? v[j].y : (h == 2) ? v[j].z : v[j].w;
                if (f >= T) {
                    size_t fe = fi + h;
                    u32 r = (fe >= bnd) ? (r0 + 1) : r0;
                    int orow = orow_of(r);
                    if (orow >= 0) {
                        int col = (int)(fe - (size_t)r * Vn);
                        int p = atomicAdd(&g_cnt[orow], 1);
                        if (p < GCAP) g_cand[(size_t)orow * GCAP + p] = packvi(f, col);
                    }
                }
            }
        }
    }

#pragma unroll
    for (int o = 16; o; o >>= 1) {
        accA += __shfl_xor_sync(0xffffffffu, accA, o);
        accB += __shfl_xor_sync(0xffffffffu, accB, o);
    }
    __shared__ float sA[8], sB[8];
    if (lane == 0) { sA[wid] = accA; sB[wid] = accB; }
    __syncthreads();
    if (tid == 0) {
        float a = 0.f;
#pragma unroll
        for (int w = 0; w < 8; w++) a += sA[w];
        int oa = orow_of(r0);
        if (oa >= 0 && a != 0.f) atomicAdd(&g_rowsum[oa], a);
    }
    if (tid == 1) {
        float bsum = 0.f;
#pragma unroll
        for (int w = 0; w < 8; w++) bsum += sB[w];
        if (bsum != 0.f && r0 + 1 < (u32)(Bn * Sn)) {
            int ob = orow_of(r0 + 1);
            if (ob >= 0) atomicAdd(&g_rowsum[ob], bsum);
        }
    }
}

// ---------------- Kernel 2: topk — one warp per row ----------------
// top-8 from the candidate buffer (fallback: full rescan for ANY pathological
// input); writes IDS / W / RM / g_pos. Runs BEFORE cols_fin (which needs RM).
__global__ __launch_bounds__(256) void topk_kernel(const float* __restrict__ logits,
                                                   const float* __restrict__ attn,
                                                   float* __restrict__ out) {
    const int lane = threadIdx.x & 31;
    const int wid = threadIdx.x >> 5;
    const int row = blockIdx.x * 8 + wid;
    const int b = row >> 8;
    const int s = row & 255;

    const int n = g_cnt[row];
    const u64 TINIT = packvi(-INFINITY, 0x7ffffffe);
    u64 ldist = TINIT;

    u64 t[Kn];
#pragma unroll
    for (int j = 0; j < Kn; j++) t[j] = TINIT;

    if (n >= Kn && n <= GCAP) {
        for (int i = lane; i < n; i += 32) {
            u64 pk = g_cand[(size_t)row * GCAP + i];
            if (pk > t[Kn - 1]) {
                u64 x = pk;
#pragma unroll
                for (int j = 0; j < Kn; j++) {
                    if (x > t[j]) { u64 tmp = t[j]; t[j] = x; x = tmp; }
                }
            }
        }
    } else {
        // fallback (statistically never): full scalar rescan of the row
        const float* __restrict__ rowp = logits + ((size_t)b * Sn + (s + 1)) * Vn;
        for (int q = lane; q < Vn; q += 32) {
            u64 pk = packvi(rowp[q], q);
            if (pk > t[Kn - 1]) {
                u64 x = pk;
#pragma unroll
                for (int j = 0; j < Kn; j++) {
                    if (x > t[j]) { u64 tmp = t[j]; t[j] = x; x = tmp; }
                }
            }
        }
    }
    // merge 32 sorted lists via repeated warp-max
    {
        int head = 0;
#pragma unroll
        for (int k = 0; k < Kn; k++) {
            u64 c = (head < Kn) ? t[head] : 0ull;
#pragma unroll
            for (int offs = 16; offs; offs >>= 1) {
                u64 o = __shfl_xor_sync(0xffffffffu, c, offs);
                if (o > c) c = o;
            }
            if (head < Kn && t[head] == c) head++;
            winsert(ldist, c, lane);
        }
    }

    const float mk = attn[b * Sn + s + 1];
    if (lane < Kn) {
        float lgk = unpackv(ldist);
        int id = unpacki(ldist);
        float w; int oid;
        if (mk > 0.f) { w = __logf(1.f + fmaxf(lgk, 0.f)) * mk; oid = id; }
        else          { w = 0.f; oid = lane; }
        out[OFF_IDS + row * Kn + lane] = (float)oid;
        out[OFF_W   + row * Kn + lane] = w;
        if (w > 0.f) {
            atomicAdd(&out[OFF_RM + b * Vn + id], 1.f);
            atomicAdd(&g_pos, 1.f);
        }
    }
}

// ---------------- Kernel 3: cols_fin — RR + SS + fused finalize ----------------
// EXACTLY the R12 kernel that measured 77.7us @ 82% DRAM; only change is the
// inline 1/rowsum in the prologue. Runs after topk: RM and g_pos complete.
__global__ __launch_bounds__(256) void cols_fin_kernel(const float* __restrict__ logits,
                                                       const float* __restrict__ attn,
                                                       float* __restrict__ out) {
    const int tid = threadIdx.x;
    const int b = blockIdx.y;
    const int pv = blockIdx.x * 256 + tid;
    const int lane = tid & 31;

    __shared__ float shi[256];
    __shared__ float shon[256];
    shi[tid]  = 1.f / g_rowsum[b * 256 + tid];
    shon[tid] = attn[b * Sn + 1 + tid] > 0.f ? 0.f : -INFINITY;  // additive mask

    // fused finalize (only the b==0 plane of blocks; covers all v)
    if (b == 0) {
        float mxa = 0.f, mxb = 0.f;
        if (pv < HALFV) {
            int v0 = 2 * pv;
#pragma unroll
            for (int bb = 0; bb < Bn; bb++) {
                mxa = fmaxf(mxa, out[OFF_RM + bb * Vn + v0]);
                mxb = fmaxf(mxb, out[OFF_RM + bb * Vn + v0 + 1]);
            }
        }
        float tot = mxa + mxb;
#pragma unroll
        for (int offs = 16; offs; offs >>= 1) tot += __shfl_xor_sync(0xffffffffu, tot, offs);
        if (lane == 0 && tot != 0.f) atomicAdd(&out[OFF_MARG], tot);
        if (blockIdx.x == 0 && tid == 0) out[OFF_COND] = g_pos * (1.f / Bn);
    }

    __syncthreads();
    if (pv >= HALFV) return;

    const float2* __restrict__ lp =
        (const float2*)(logits + ((size_t)b * Sn + 1) * Vn) + pv;
    float M0 = -INFINITY, M1 = -INFINITY;
    float a0 = 0.f, a1 = 0.f, a2 = 0.f, a3 = 0.f;
#pragma unroll 1
    for (int s = 0; s < 256; s += 8) {
        float2 l0 = __ldcs(lp + (size_t)(s + 0) * HALFV);
        float2 l1 = __ldcs(lp + (size_t)(s + 1) * HALFV);
        float2 l2 = __ldcs(lp + (size_t)(s + 2) * HALFV);
        float2 l3 = __ldcs(lp + (size_t)(s + 3) * HALFV);
        float2 l4 = __ldcs(lp + (size_t)(s + 4) * HALFV);
        float2 l5 = __ldcs(lp + (size_t)(s + 5) * HALFV);
        float2 l6 = __ldcs(lp + (size_t)(s + 6) * HALFV);
        float2 l7 = __ldcs(lp + (size_t)(s + 7) * HALFV);
        a0 += __expf(l0.x) * shi[s + 0];  a1 += __expf(l0.y) * shi[s + 0];
        a2 += __expf(l1.x) * shi[s + 1];  a3 += __expf(l1.y) * shi[s + 1];
        a0 += __expf(l2.x) * shi[s + 2];  a1 += __expf(l2.y) * shi[s + 2];
        a2 += __expf(l3.x) * shi[s + 3];  a3 += __expf(l3.y) * shi[s + 3];
        a0 += __expf(l4.x) * shi[s + 4];  a1 += __expf(l4.y) * shi[s + 4];
        a2 += __expf(l5.x) * shi[s + 5];  a3 += __expf(l5.y) * shi[s + 5];
        a0 += __expf(l6.x) * shi[s + 6];  a1 += __expf(l6.y) * shi[s + 6];
        a2 += __expf(l7.x) * shi[s + 7];  a3 += __expf(l7.y) * shi[s + 7];
        M0 = fmaxf(M0, l0.x + shon[s + 0]);  M1 = fmaxf(M1, l0.y + shon[s + 0]);
        M0 = fmaxf(M0, l1.x + shon[s + 1]);  M1 = fmaxf(M1, l1.y + shon[s + 1]);
        M0 = fmaxf(M0, l2.x + shon[s + 2]);  M1 = fmaxf(M1, l2.y + shon[s + 2]);
        M0 = fmaxf(M0, l3.x + shon[s + 3]);  M1 = fmaxf(M1, l3.y + shon[s + 3]);
        M0 = fmaxf(M0, l4.x + shon[s + 4]);  M1 = fmaxf(M1, l4.y + shon[s + 4]);
        M0 = fmaxf(M0, l5.x + shon[s + 5]);  M1 = fmaxf(M1, l5.y + shon[s + 5]);
        M0 = fmaxf(M0, l6.x + shon[s + 6]);  M1 = fmaxf(M1, l6.y + shon[s + 6]);
        M0 = fmaxf(M0, l7.x + shon[s + 7]);  M1 = fmaxf(M1, l7.y + shon[s + 7]);
    }
    int v = 2 * pv;
    out[OFF_RR + b * Vn + v]     = __logf(1.f + fmaxf(M0, 0.f));
    out[OFF_RR + b * Vn + v + 1] = __logf(1.f + fmaxf(M1, 0.f));
    out[OFF_SS + b * Vn + v]     = (a0 + a2);
    out[OFF_SS + b * Vn + v + 1] = (a1 + a3);
}

// ---------------- Kernel 4: expert_repr + fused zeroing ----------------
#define EK_ROWS 4
__global__ __launch_bounds__(256) void expert_kernel(const float* __restrict__ hidden,
                                                     const float* __restrict__ attn,
                                                     const float* __restrict__ W,
                                                     const float* __restrict__ bt,
                                                     float* __restrict__ out) {
    // fused zero: COND/MARG/RM region + g_rowsum/g_cnt/g_pos scratch
    {
        int gidx = blockIdx.x * 256 + threadIdx.x;
        if (gidx < OFF_SS) out[gidx] = 0.f;
        int g2 = gidx + (NROWS / EK_ROWS) * 256;
        if (g2 < OFF_SS) out[g2] = 0.f;
        if (gidx < NROWS) { g_rowsum[gidx] = 0.f; g_cnt[gidx] = 0; }
        if (gidx == 0) g_pos = 0.f;
    }

    __shared__ float hrow[Hn];
    const int tid = threadIdx.x;
    const int lane = tid & 31;
    const int wid = tid >> 5;
    const int p0 = wid * 4;

    const float* __restrict__ w0 = W + (p0 + 0) * Hn + lane;
    const float* __restrict__ w1 = W + (p0 + 1) * Hn + lane;
    const float* __restrict__ w2 = W + (p0 + 2) * Hn + lane;
    const float* __restrict__ w3 = W + (p0 + 3) * Hn + lane;

    for (int r = 0; r < EK_ROWS; r++) {
        const int row = blockIdx.x * EK_ROWS + r;
        const int b = row >> 8;
        const int s = row & 255;
        const size_t hbase = ((size_t)b * Sn + s + 1) * Hn;
#pragma unroll
        for (int c = 0; c < 3; c++) hrow[c * 256 + tid] = hidden[hbase + c * 256 + tid];
        __syncthreads();

        float a0 = 0.f, a1 = 0.f, a2 = 0.f, a3 = 0.f;
#pragma unroll
        for (int k = 0; k < Hn / 32; k++) {
            float hv = hrow[k * 32 + lane];
            a0 += hv * __ldg(w0 + k * 32);
            a1 += hv * __ldg(w1 + k * 32);
            a2 += hv * __ldg(w2 + k * 32);
            a3 += hv * __ldg(w3 + k * 32);
        }
#pragma unroll
        for (int off = 16; off; off >>= 1) {
            a0 += __shfl_xor_sync(0xffffffffu, a0, off);
            a1 += __shfl_xor_sync(0xffffffffu, a1, off);
            a2 += __shfl_xor_sync(0xffffffffu, a2, off);
            a3 += __shfl_xor_sync(0xffffffffu, a3, off);
        }
        if (lane == 0) {
            float mk = attn[b * Sn + s + 1];
            if (wid == 0) out[OFF_MASK + row] = mk;
            out[OFF_ER + row * Pn + p0 + 0] = (a0 + bt[p0 + 0]) * mk;
            out[OFF_ER + row * Pn + p0 + 1] = (a1 + bt[p0 + 1]) * mk;
            out[OFF_ER + row * Pn + p0 + 2] = (a2 + bt[p0 + 2]) * mk;
            out[OFF_ER + row * Pn + p0 + 3] = (a3 + bt[p0 + 3]) * mk;
        }
        __syncthreads();
    }
}

extern "C" void kernel_launch(void* const* d_in, const int* in_sizes, int n_in,
                              void* d_out, int out_size) {
    const float *hidden = nullptr, *logits = nullptr, *attn = nullptr, *W = nullptr, *bt = nullptr;
    for (int i = 0; i < n_in; i++) {
        long n = in_sizes[i];
        if      (n == (long)Bn * Sn * Vn) logits = (const float*)d_in[i];
        else if (n == (long)Bn * Sn * Hn) hidden = (const float*)d_in[i];
        else if (n == (long)Bn * Sn)      attn   = (const float*)d_in[i];
        else if (n == (long)Pn * Hn)      W      = (const float*)d_in[i];
        else if (n == (long)Pn)           bt     = (const float*)d_in[i];
    }
    float* out = (float*)d_out;

    const int nsum = (int)((E4 + SB4 - 1) / SB4);     // 15321
    dim3 vgrid((HALFV + 255) / 256, Bn);

    expert_kernel<<<NROWS / EK_ROWS, 256>>>(hidden, attn, W, bt, out);  // 1 (+zero)
    spacer_kernel<<<1, 32>>>();                                         // 2
    spacer_kernel<<<1, 32>>>();                                         // 3
    sums_kernel<<<nsum, 256>>>(logits);                                 // 4 (profiled, +gather)
    topk_kernel<<<NROWS / 8, 256>>>(logits, attn, out);                 // 5
    cols_fin_kernel<<<vgrid, 256>>>(logits, attn, out);                 // 6 (+finalize)
}